// round 3
// baseline (speedup 1.0000x reference)
#include <cuda_runtime.h>

#define B_TOTAL 16384
#define H 128
#define NATT 3
#define NC 10
#define ROWS 16          // rows per block
#define RPH 8            // rows per half-block
#define PAD 132          // 132 floats: keeps float4 alignment, staggers banks by 4
#define LOG2E 1.4426950408889634f

__device__ __forceinline__ float ex2f_(float x) {
    float y; asm("ex2.approx.f32 %0, %1;" : "=f"(y) : "f"(x)); return y;
}
__device__ __forceinline__ float rcpf_(float x) {
    float y; asm("rcp.approx.f32 %0, %1;" : "=f"(y) : "f"(x)); return y;
}
__device__ __forceinline__ float rsqrtf_(float x) {
    float y; asm("rsqrt.approx.f32 %0, %1;" : "=f"(y) : "f"(x)); return y;
}
// Accurate tanh: 1 - 2/(e^{2x}+1). ex2/rcp approx are ~2^-22 rel err, far
// below the 1e-3 gate (tanh.approx.f32's ~6e-4 abs err is too risky here).
__device__ __forceinline__ float tanh_acc(float x) {
    float e = ex2f_(2.0f * LOG2E * x);
    return 1.0f - 2.0f * rcpf_(e + 1.0f);
}

__global__ __launch_bounds__(256, 2)
void simpleattn_kernel(const float* __restrict__ x,
                       const float* __restrict__ W_in,
                       const float* __restrict__ b_in,
                       const float* __restrict__ W_att,
                       const float* __restrict__ b_att,
                       const float* __restrict__ gamma,
                       const float* __restrict__ beta,
                       const float* __restrict__ W_c,
                       const float* __restrict__ b_c,
                       float* __restrict__ out)
{
    __shared__ float hs[ROWS][PAD];   // current hidden state
    __shared__ float us[ROWS][PAD];   // u * log2(e)  (also x staging)
    __shared__ float red[ROWS][8];    // LN partials: [0..3]=sum, [4..7]=sumsq

    const int tid  = threadIdx.x;
    const int t    = tid & 127;       // feature column owned by this thread
    const int half = tid >> 7;        // 0 or 1
    const int r0   = half * RPH;      // first row of this half
    const int lane = tid & 31;
    const int wIdx = (tid >> 5) & 3;  // warp index within half
    const int row0 = blockIdx.x * ROWS;

    // ---- stage x tile into us ----
    #pragma unroll
    for (int r = 0; r < RPH; r++)
        us[r0 + r][t] = x[(row0 + r0 + r) * H + t];
    __syncthreads();

    // ---- in_proj: h = x @ W_in + b_in ----
    float h[RPH];
    {
        float acc[RPH];
        #pragma unroll
        for (int r = 0; r < RPH; r++) acc[r] = 0.f;
        for (int k = 0; k < H; k += 4) {
            float w0 = W_in[(k + 0) * H + t];
            float w1 = W_in[(k + 1) * H + t];
            float w2 = W_in[(k + 2) * H + t];
            float w3 = W_in[(k + 3) * H + t];
            #pragma unroll
            for (int r = 0; r < RPH; r++) {
                float4 xv = *(const float4*)&us[r0 + r][k];
                acc[r] += xv.x * w0 + xv.y * w1 + xv.z * w2 + xv.w * w3;
            }
        }
        float bb = b_in[t];
        #pragma unroll
        for (int r = 0; r < RPH; r++) { h[r] = acc[r] + bb; hs[r0 + r][t] = h[r]; }
    }
    __syncthreads();

    // ---- attention layers ----
    float u[RPH];
    for (int layer = 0; layer < NATT; layer++) {
        const float* Wl = W_att + layer * H * H;

        // u = tanh(h @ Wl + b_att[layer])
        {
            float acc[RPH];
            #pragma unroll
            for (int r = 0; r < RPH; r++) acc[r] = 0.f;
            for (int k = 0; k < H; k += 4) {
                float w0 = Wl[(k + 0) * H + t];
                float w1 = Wl[(k + 1) * H + t];
                float w2 = Wl[(k + 2) * H + t];
                float w3 = Wl[(k + 3) * H + t];
                #pragma unroll
                for (int r = 0; r < RPH; r++) {
                    float4 hv = *(const float4*)&hs[r0 + r][k];
                    acc[r] += hv.x * w0 + hv.y * w1 + hv.z * w2 + hv.w * w3;
                }
            }
            float bb = b_att[layer * H + t];
            #pragma unroll
            for (int r = 0; r < RPH; r++) {
                u[r] = tanh_acc(acc[r] + bb);
                us[r0 + r][t] = u[r] * LOG2E;   // pre-scale for ex2
            }
        }
        __syncthreads();

        // attention: out_i = sum_j e^{u_i u_j} h_j / sum_j e^{u_i u_j}
        // (no max-subtraction needed: u in [-1,1] => exp in [0.37, 2.72])
        float y[RPH];
        #pragma unroll
        for (int r = 0; r < RPH; r++) {
            float a = u[r];
            float num = 0.f, den = 0.f;
            #pragma unroll 4
            for (int j = 0; j < H; j += 4) {
                float4 uv = *(const float4*)&us[r0 + r][j];
                float4 hv = *(const float4*)&hs[r0 + r][j];
                float w0 = ex2f_(a * uv.x);
                float w1 = ex2f_(a * uv.y);
                float w2 = ex2f_(a * uv.z);
                float w3 = ex2f_(a * uv.w);
                num += w0 * hv.x; den += w0;
                num += w1 * hv.y; den += w1;
                num += w2 * hv.z; den += w2;
                num += w3 * hv.w; den += w3;
            }
            y[r] = h[r] + num * rcpf_(den);   // residual
        }

        // LayerNorm over feature dim (128 threads = 4 warps per row-half)
        #pragma unroll
        for (int r = 0; r < RPH; r++) {
            float s = y[r], q = y[r] * y[r];
            #pragma unroll
            for (int o = 16; o > 0; o >>= 1) {
                s += __shfl_xor_sync(0xffffffffu, s, o);
                q += __shfl_xor_sync(0xffffffffu, q, o);
            }
            if (lane == 0) { red[r0 + r][wIdx] = s; red[r0 + r][4 + wIdx] = q; }
        }
        __syncthreads();   // also guarantees all attention reads of hs/us done

        float g = gamma[layer * H + t];
        float bt = beta[layer * H + t];
        #pragma unroll
        for (int r = 0; r < RPH; r++) {
            float s = red[r0 + r][0] + red[r0 + r][1] + red[r0 + r][2] + red[r0 + r][3];
            float q = red[r0 + r][4] + red[r0 + r][5] + red[r0 + r][6] + red[r0 + r][7];
            float m   = s * (1.0f / H);
            float var = q * (1.0f / H) - m * m;
            float inv = rsqrtf_(var + 1e-5f);
            h[r] = (y[r] - m) * inv * g + bt;
            hs[r0 + r][t] = h[r];
        }
        __syncthreads();
    }

    // ---- classifier: out = h @ W_c + b_c  (160 threads, one per (row, class)) ----
    if (tid < ROWS * NC) {
        int r = tid / NC, c = tid - r * NC;
        float acc = b_c[c];
        #pragma unroll 8
        for (int k = 0; k < H; k++)
            acc += hs[r][k] * W_c[k * NC + c];
        out[(row0 + r) * NC + c] = acc;
    }
}

extern "C" void kernel_launch(void* const* d_in, const int* in_sizes, int n_in,
                              void* d_out, int out_size)
{
    const float* x     = (const float*)d_in[0];
    const float* W_in  = (const float*)d_in[1];
    const float* b_in  = (const float*)d_in[2];
    const float* W_att = (const float*)d_in[3];
    const float* b_att = (const float*)d_in[4];
    const float* gamma = (const float*)d_in[5];
    const float* beta  = (const float*)d_in[6];
    const float* W_c   = (const float*)d_in[7];
    const float* b_c   = (const float*)d_in[8];
    float* out = (float*)d_out;

    dim3 grid(B_TOTAL / ROWS);   // 1024 blocks
    dim3 block(256);
    simpleattn_kernel<<<grid, block>>>(x, W_in, b_in, W_att, b_att,
                                       gamma, beta, W_c, b_c, out);
}

// round 4
// speedup vs baseline: 1.1254x; 1.1254x over previous
#include <cuda_runtime.h>

#define B_TOTAL 16384
#define H 128
#define NATT 3
#define NC 10
#define ROWS 16          // rows per block
#define RPH 8            // rows per half-block
#define PAD 132          // keeps 16B alignment (132*4=528=16*33), staggers banks
#define LOG2E 1.4426950408889634f

typedef unsigned long long u64;

__device__ __forceinline__ float ex2f_(float x) {
    float y; asm("ex2.approx.f32 %0, %1;" : "=f"(y) : "f"(x)); return y;
}
__device__ __forceinline__ float rcpf_(float x) {
    float y; asm("rcp.approx.f32 %0, %1;" : "=f"(y) : "f"(x)); return y;
}
__device__ __forceinline__ float rsqrtf_(float x) {
    float y; asm("rsqrt.approx.f32 %0, %1;" : "=f"(y) : "f"(x)); return y;
}
// Accurate tanh: 1 - 2/(e^{2x}+1); ex2/rcp approx ~2^-22 rel err.
__device__ __forceinline__ float tanh_acc(float x) {
    float e = ex2f_(2.0f * LOG2E * x);
    return 1.0f - 2.0f * rcpf_(e + 1.0f);
}

// ---- packed f32x2 helpers (sm_103a; PTX-only per SASS_QUICKREF) ----
__device__ __forceinline__ u64 pack2_(float lo, float hi) {
    u64 r; asm("mov.b64 %0, {%1,%2};" : "=l"(r) : "f"(lo), "f"(hi)); return r;
}
__device__ __forceinline__ void unpack2_(u64 v, float& lo, float& hi) {
    asm("mov.b64 {%0,%1}, %2;" : "=f"(lo), "=f"(hi) : "l"(v));
}
__device__ __forceinline__ u64 mul2_(u64 a, u64 b) {
    u64 r; asm("mul.rn.f32x2 %0, %1, %2;" : "=l"(r) : "l"(a), "l"(b)); return r;
}
__device__ __forceinline__ u64 fma2_(u64 a, u64 b, u64 c) {
    u64 r; asm("fma.rn.f32x2 %0, %1, %2, %3;" : "=l"(r) : "l"(a), "l"(b), "l"(c)); return r;
}
__device__ __forceinline__ u64 add2_(u64 a, u64 b) {
    u64 r; asm("add.rn.f32x2 %0, %1, %2;" : "=l"(r) : "l"(a), "l"(b)); return r;
}

// Packed matvec: hout[r] = sum_k src[r0+r][k] * W[k*H + t] + bias
__device__ __forceinline__ void matvec8(const float (*__restrict__ src)[PAD], int r0, int t,
                                        const float* __restrict__ W,
                                        float bias, float* __restrict__ hout)
{
    u64 acc[RPH];
    #pragma unroll
    for (int r = 0; r < RPH; r++) acc[r] = pack2_(0.f, 0.f);
    for (int k = 0; k < H; k += 4) {
        float w0 = W[(k + 0) * H + t];
        float w1 = W[(k + 1) * H + t];
        float w2 = W[(k + 2) * H + t];
        float w3 = W[(k + 3) * H + t];
        u64 w01 = pack2_(w0, w1), w23 = pack2_(w2, w3);
        #pragma unroll
        for (int r = 0; r < RPH; r++) {
            ulonglong2 xv = *(const ulonglong2*)&src[r0 + r][k];
            acc[r] = fma2_(w01, xv.x, acc[r]);
            acc[r] = fma2_(w23, xv.y, acc[r]);
        }
    }
    #pragma unroll
    for (int r = 0; r < RPH; r++) {
        float lo, hi; unpack2_(acc[r], lo, hi);
        hout[r] = lo + hi + bias;
    }
}

__global__ __launch_bounds__(256, 3)
void simpleattn_kernel(const float* __restrict__ x,
                       const float* __restrict__ W_in,
                       const float* __restrict__ b_in,
                       const float* __restrict__ W_att,
                       const float* __restrict__ b_att,
                       const float* __restrict__ gamma,
                       const float* __restrict__ beta,
                       const float* __restrict__ W_c,
                       const float* __restrict__ b_c,
                       float* __restrict__ out)
{
    __shared__ float hs[ROWS][PAD];   // current hidden state
    __shared__ float us[ROWS][PAD];   // u * log2(e)  (also x staging)
    __shared__ float red[ROWS][8];    // LN partials

    const int tid  = threadIdx.x;
    const int t    = tid & 127;
    const int half = tid >> 7;
    const int r0   = half * RPH;
    const int lane = tid & 31;
    const int wIdx = (tid >> 5) & 3;
    const int row0 = blockIdx.x * ROWS;

    // ---- stage x tile into us ----
    #pragma unroll
    for (int r = 0; r < RPH; r++)
        us[r0 + r][t] = x[(row0 + r0 + r) * H + t];
    __syncthreads();

    // ---- in_proj: h = x @ W_in + b_in ----
    float h[RPH];
    matvec8(us, r0, t, W_in, b_in[t], h);
    #pragma unroll
    for (int r = 0; r < RPH; r++) hs[r0 + r][t] = h[r];
    __syncthreads();

    // ---- attention layers ----
    float u[RPH], v[RPH], y[RPH];
    for (int layer = 0; layer < NATT; layer++) {
        const float* Wl = W_att + layer * H * H;

        // u = tanh(h @ Wl + b_att[layer])
        matvec8(hs, r0, t, Wl, b_att[layer * H + t], v);
        #pragma unroll
        for (int r = 0; r < RPH; r++) {
            u[r] = tanh_acc(v[r]);
            us[r0 + r][t] = u[r] * LOG2E;   // pre-scale for ex2
        }
        __syncthreads();

        // out_i = sum_j e^{u_i u_j} h_j / sum_j e^{u_i u_j}
        // (u in [-1,1] => exp in [0.37, 2.72], no max-subtraction needed)
        #pragma unroll
        for (int r = 0; r < RPH; r++) {
            float a = u[r];
            u64 a2 = pack2_(a, a);
            u64 num = pack2_(0.f, 0.f), den = num;
            #pragma unroll 4
            for (int j = 0; j < H; j += 4) {
                ulonglong2 uv = *(const ulonglong2*)&us[r0 + r][j];
                ulonglong2 hv = *(const ulonglong2*)&hs[r0 + r][j];
                u64 p01 = mul2_(a2, uv.x);
                u64 p23 = mul2_(a2, uv.y);
                float p0, p1, p2, p3;
                unpack2_(p01, p0, p1);
                unpack2_(p23, p2, p3);
                float w0 = ex2f_(p0), w1 = ex2f_(p1);
                float w2 = ex2f_(p2), w3 = ex2f_(p3);
                u64 w01 = pack2_(w0, w1), w23 = pack2_(w2, w3);
                num = fma2_(w01, hv.x, num);
                den = add2_(den, w01);
                num = fma2_(w23, hv.y, num);
                den = add2_(den, w23);
            }
            float nlo, nhi, dlo, dhi;
            unpack2_(num, nlo, nhi);
            unpack2_(den, dlo, dhi);
            y[r] = h[r] + (nlo + nhi) * rcpf_(dlo + dhi);   // residual
        }

        // LayerNorm over feature dim
        #pragma unroll
        for (int r = 0; r < RPH; r++) {
            float s = y[r], q = y[r] * y[r];
            #pragma unroll
            for (int o = 16; o > 0; o >>= 1) {
                s += __shfl_xor_sync(0xffffffffu, s, o);
                q += __shfl_xor_sync(0xffffffffu, q, o);
            }
            if (lane == 0) { red[r0 + r][wIdx] = s; red[r0 + r][4 + wIdx] = q; }
        }
        __syncthreads();   // also fences attention reads of hs/us

        float g  = gamma[layer * H + t];
        float bt = beta[layer * H + t];
        #pragma unroll
        for (int r = 0; r < RPH; r++) {
            float s = red[r0 + r][0] + red[r0 + r][1] + red[r0 + r][2] + red[r0 + r][3];
            float q = red[r0 + r][4] + red[r0 + r][5] + red[r0 + r][6] + red[r0 + r][7];
            float m   = s * (1.0f / H);
            float var = q * (1.0f / H) - m * m;
            float inv = rsqrtf_(var + 1e-5f);
            h[r] = (y[r] - m) * inv * g + bt;
            hs[r0 + r][t] = h[r];
        }
        __syncthreads();
    }

    // ---- classifier: out = h @ W_c + b_c ----
    if (tid < ROWS * NC) {
        int r = tid / NC, c = tid - r * NC;
        float acc = b_c[c];
        #pragma unroll 8
        for (int k = 0; k < H; k++)
            acc += hs[r][k] * W_c[k * NC + c];
        out[(row0 + r) * NC + c] = acc;
    }
}

extern "C" void kernel_launch(void* const* d_in, const int* in_sizes, int n_in,
                              void* d_out, int out_size)
{
    const float* x     = (const float*)d_in[0];
    const float* W_in  = (const float*)d_in[1];
    const float* b_in  = (const float*)d_in[2];
    const float* W_att = (const float*)d_in[3];
    const float* b_att = (const float*)d_in[4];
    const float* gamma = (const float*)d_in[5];
    const float* beta  = (const float*)d_in[6];
    const float* W_c   = (const float*)d_in[7];
    const float* b_c   = (const float*)d_in[8];
    float* out = (float*)d_out;

    dim3 grid(B_TOTAL / ROWS);   // 1024 blocks
    dim3 block(256);
    simpleattn_kernel<<<grid, block>>>(x, W_in, b_in, W_att, b_att,
                                       gamma, beta, W_c, b_c, out);
}